// round 6
// baseline (speedup 1.0000x reference)
#include <cuda_runtime.h>

// Output layout: x_hat (64*1*256*256) | ze (64*64*64*64) | zq (64*64*64*64)
#define OFF_ZE 4194304
#define OFF_ZQ 20971520

// Scratch (__device__ globals)
__device__ float g_h1[33554432];   // (64,32,128,128)
__device__ float g_h2[16777216];   // (64,64,64,64)
__device__ float g_dec[16777216];  // (64,64,64,64)
__device__ float g_d1[8388608];    // (64,32,64,64)
__device__ float g_d2[67108864];   // (64,64,128,128)

// ===========================================================================
// ENCODER — bit-exact emulation of XLA-CPU/Eigen conv (FROZEN arithmetic):
// per output: acc = 0; sequential fused-FMA over (ky asc, kx asc, ci asc
// fastest); then y = max(add(acc, bias), 0).
// ===========================================================================

// e1: conv 1->32, k4 s2 p1. x(64,1,256,256) -> g_h1(64,32,128,128)
__global__ __launch_bounds__(256) void k_e1(const float* __restrict__ x,
                                            const float* __restrict__ w,
                                            const float* __restrict__ b) {
    __shared__ float sw[16][32];   // [tap][o]
    __shared__ float sb[32];
    int t = threadIdx.x;
    {
        int o = t & 31, tap = t >> 5;
        sw[tap][o] = w[o * 16 + tap];
        int e = t + 256; o = e & 31; tap = e >> 5;
        sw[tap][o] = w[o * 16 + tap];
    }
    if (t < 32) sb[t] = b[t];
    __syncthreads();
    int gid = blockIdx.x * 256 + t;
    int ox = gid & 127, oy = (gid >> 7) & 127, n = gid >> 14;
    float acc[32];
#pragma unroll
    for (int o = 0; o < 32; o++) acc[o] = 0.f;
    const float* xin = x + n * 65536;
#pragma unroll
    for (int ky = 0; ky < 4; ky++) {
        int iy = 2 * oy - 1 + ky;
        if (iy < 0 || iy >= 256) continue;
#pragma unroll
        for (int kx = 0; kx < 4; kx++) {
            int ix = 2 * ox - 1 + kx;
            if (ix < 0 || ix >= 256) continue;
            float v = xin[iy * 256 + ix];
#pragma unroll
            for (int o = 0; o < 32; o++) acc[o] = fmaf(v, sw[ky * 4 + kx][o], acc[o]);
        }
    }
    float* op = g_h1 + n * 524288 + oy * 128 + ox;
#pragma unroll
    for (int o = 0; o < 32; o++) op[o * 16384] = fmaxf(__fadd_rn(acc[o], sb[o]), 0.f);
}

// e2: conv 32->64, k4 s2 p1. g_h1 -> g_h2(64,64,64,64)
#define E2_PITCH 35
#define E2_IN_FLOATS (32 * 34 * E2_PITCH)
#define E2_W_FLOATS  (4 * 32 * 64)
#define E2_SMEM_B   ((E2_IN_FLOATS + E2_W_FLOATS) * 4)
__global__ __launch_bounds__(256, 1) void k_e2(const float* __restrict__ w,
                                               const float* __restrict__ b) {
    extern __shared__ float sm[];
    float* sIn = sm;                 // [ci][34][35]
    float* sw  = sm + E2_IN_FLOATS;  // [kx][ci][o]
    int tid = threadIdx.x;
    int og8 = tid >> 5;
    int sp = tid & 31;
    int r = sp >> 1, h = sp & 1;
    int t_y = blockIdx.x >> 2, t_x = blockIdx.x & 3;
    int n = blockIdx.y;
    int iy0 = 32 * t_y - 1, ix0 = 32 * t_x - 1;
    for (int idx = tid; idx < 32 * 34 * 34; idx += 256) {
        int ci = idx / 1156, rr = idx - ci * 1156;
        int iy = rr / 34, ix = rr - iy * 34;
        int gy = iy0 + iy, gx = ix0 + ix;
        float v = 0.f;
        if (gy >= 0 && gy < 128 && gx >= 0 && gx < 128)
            v = g_h1[((n * 32 + ci) * 128 + gy) * 128 + gx];
        sIn[ci * (34 * E2_PITCH) + iy * E2_PITCH + ix] = v;
    }
    float acc[64];
#pragma unroll
    for (int i = 0; i < 64; i++) acc[i] = 0.f;
#pragma unroll
    for (int ky = 0; ky < 4; ky++) {
        __syncthreads();
        for (int idx = tid; idx < E2_W_FLOATS; idx += 256) {
            int kx = idx >> 11, ci = (idx >> 6) & 31, o = idx & 63;
            sw[idx] = w[(o * 32 + ci) * 16 + ky * 4 + kx];
        }
        __syncthreads();
#pragma unroll
        for (int kx = 0; kx < 4; kx++) {
            for (int ci = 0; ci < 32; ci++) {
                const float* vb = &sIn[ci * (34 * E2_PITCH) + (2 * r + ky) * E2_PITCH + 16 * h + kx];
                float v[8];
#pragma unroll
                for (int j = 0; j < 8; j++) v[j] = vb[2 * j];
                const float4* wp = (const float4*)&sw[(kx * 32 + ci) * 64 + og8 * 8];
                float4 w0 = wp[0], w1 = wp[1];
                float wv[8] = {w0.x, w0.y, w0.z, w0.w, w1.x, w1.y, w1.z, w1.w};
#pragma unroll
                for (int j = 0; j < 8; j++)
#pragma unroll
                    for (int oo = 0; oo < 8; oo++)
                        acc[j * 8 + oo] = fmaf(v[j], wv[oo], acc[j * 8 + oo]);
            }
        }
    }
    int oy = 16 * t_y + r, ox0 = 16 * t_x + 8 * h;
#pragma unroll
    for (int oo = 0; oo < 8; oo++) {
        int o = og8 * 8 + oo;
        float bb = b[o];
        float* op = g_h2 + ((n * 64 + o) * 64 + oy) * 64 + ox0;
#pragma unroll
        for (int j = 0; j < 8; j++)
            op[j] = fmaxf(__fadd_rn(acc[j * 8 + oo], bb), 0.f);
    }
}

// e3: conv 64->64, k3 s1 p1. g_h2 -> ze (d_out)
#define E3_PITCH 21
#define E3_IN_FLOATS (64 * 18 * E3_PITCH)
#define E3_W_FLOATS  (3 * 64 * 64)
#define E3_SMEM_B   ((E3_IN_FLOATS + E3_W_FLOATS) * 4)
__global__ __launch_bounds__(256, 1) void k_e3(const float* __restrict__ w,
                                               const float* __restrict__ b,
                                               float* __restrict__ ze) {
    extern __shared__ float sm[];
    float* sIn = sm;                 // [ci][18][21]
    float* sw  = sm + E3_IN_FLOATS;  // [kx][ci][o]
    int tid = threadIdx.x;
    int og8 = tid >> 5;
    int sp = tid & 31;
    int r = sp >> 1, h = sp & 1;
    int t_y = blockIdx.x >> 2, t_x = blockIdx.x & 3;
    int n = blockIdx.y;
    int iy0 = 16 * t_y - 1, ix0 = 16 * t_x - 1;
    for (int idx = tid; idx < 64 * 18 * 18; idx += 256) {
        int ci = idx / 324, rr = idx - ci * 324;
        int iy = rr / 18, ix = rr - iy * 18;
        int gy = iy0 + iy, gx = ix0 + ix;
        float v = 0.f;
        if (gy >= 0 && gy < 64 && gx >= 0 && gx < 64)
            v = g_h2[((n * 64 + ci) * 64 + gy) * 64 + gx];
        sIn[ci * (18 * E3_PITCH) + iy * E3_PITCH + ix] = v;
    }
    float acc[64];
#pragma unroll
    for (int i = 0; i < 64; i++) acc[i] = 0.f;
#pragma unroll
    for (int ky = 0; ky < 3; ky++) {
        __syncthreads();
        for (int idx = tid; idx < E3_W_FLOATS; idx += 256) {
            int kx = idx >> 12, ci = (idx >> 6) & 63, o = idx & 63;
            sw[idx] = w[(o * 64 + ci) * 9 + ky * 3 + kx];
        }
        __syncthreads();
#pragma unroll
        for (int kx = 0; kx < 3; kx++) {
            for (int ci = 0; ci < 64; ci++) {
                const float* vb = &sIn[ci * (18 * E3_PITCH) + (r + ky) * E3_PITCH + 8 * h + kx];
                float v[8];
#pragma unroll
                for (int j = 0; j < 8; j++) v[j] = vb[j];
                const float4* wp = (const float4*)&sw[(kx * 64 + ci) * 64 + og8 * 8];
                float4 w0 = wp[0], w1 = wp[1];
                float wv[8] = {w0.x, w0.y, w0.z, w0.w, w1.x, w1.y, w1.z, w1.w};
#pragma unroll
                for (int j = 0; j < 8; j++)
#pragma unroll
                    for (int oo = 0; oo < 8; oo++)
                        acc[j * 8 + oo] = fmaf(v[j], wv[oo], acc[j * 8 + oo]);
            }
        }
    }
    int oy = 16 * t_y + r, ox0 = 16 * t_x + 8 * h;
#pragma unroll
    for (int oo = 0; oo < 8; oo++) {
        int o = og8 * 8 + oo;
        float bb = b[o];
        float* op = ze + ((n * 64 + o) * 64 + oy) * 64 + ox0;
#pragma unroll
        for (int j = 0; j < 8; j++)
            op[j] = fmaxf(__fadd_rn(acc[j * 8 + oo], bb), 0.f);
    }
}

// ===========================================================================
// VQ — exact f32 replica (FROZEN chains), now 2 spatial positions per thread
// so each broadcast LDS.128 feeds 8 FMA chains instead of 4.
// ===========================================================================
#define VQ_SMEM_B ((64 * 512 + 512) * 4)
__global__ __launch_bounds__(256, 1) void k_vq(const float* __restrict__ ze,
                                               const float* __restrict__ emb,
                                               float* __restrict__ zq) {
    extern __shared__ float sm[];
    float* se = sm;           // [c][k] = 64 x 512
    float* sn = sm + 32768;   // sqe[k]
    int tid = threadIdx.x;
    for (int i = tid; i < 32768; i += 256) {
        int k = i >> 6, c = i & 63;
        se[c * 512 + k] = emb[i];
    }
    __syncthreads();
    for (int k = tid; k < 512; k += 256) {
        float s = 0.f;
#pragma unroll
        for (int c = 0; c < 64; c++) {
            float e = se[c * 512 + k];
            s = __fadd_rn(s, __fmul_rn(e, e));
        }
        sn[k] = s;
    }
    __syncthreads();
    int pid = blockIdx.x * 256 + tid;      // 131072 pairs
    int n = pid >> 11;
    int rem = pid & 2047;
    int y = rem >> 5;
    int x0 = (rem & 31) << 1;
    const float* zp = ze + n * 262144 + y * 64 + x0;
    float z0[64], z1[64];
#pragma unroll
    for (int c = 0; c < 64; c++) {
        float2 t = *(const float2*)(zp + c * 4096);
        z0[c] = t.x; z1[c] = t.y;
    }
    float sqz0 = 0.f, sqz1 = 0.f;
#pragma unroll
    for (int c = 0; c < 64; c++) sqz0 = __fadd_rn(sqz0, __fmul_rn(z0[c], z0[c]));
#pragma unroll
    for (int c = 0; c < 64; c++) sqz1 = __fadd_rn(sqz1, __fmul_rn(z1[c], z1[c]));
    float best0 = 3.4028235e38f, best1 = 3.4028235e38f;
    int bi0 = 0, bi1 = 0;
    for (int k0 = 0; k0 < 512; k0 += 4) {
        float a0 = 0.f, a1 = 0.f, a2 = 0.f, a3 = 0.f;
        float c0 = 0.f, c1 = 0.f, c2 = 0.f, c3 = 0.f;
#pragma unroll
        for (int c = 0; c < 64; c++) {
            float4 e = *(const float4*)&se[c * 512 + k0];
            a0 = fmaf(z0[c], e.x, a0);
            a1 = fmaf(z0[c], e.y, a1);
            a2 = fmaf(z0[c], e.z, a2);
            a3 = fmaf(z0[c], e.w, a3);
            c0 = fmaf(z1[c], e.x, c0);
            c1 = fmaf(z1[c], e.y, c1);
            c2 = fmaf(z1[c], e.z, c2);
            c3 = fmaf(z1[c], e.w, c3);
        }
        float n0 = sn[k0], n1 = sn[k0 + 1], n2 = sn[k0 + 2], n3 = sn[k0 + 3];
        float q;
        q = __fadd_rn(__fsub_rn(sqz0, __fmul_rn(2.f, a0)), n0); if (q < best0) { best0 = q; bi0 = k0; }
        q = __fadd_rn(__fsub_rn(sqz0, __fmul_rn(2.f, a1)), n1); if (q < best0) { best0 = q; bi0 = k0 + 1; }
        q = __fadd_rn(__fsub_rn(sqz0, __fmul_rn(2.f, a2)), n2); if (q < best0) { best0 = q; bi0 = k0 + 2; }
        q = __fadd_rn(__fsub_rn(sqz0, __fmul_rn(2.f, a3)), n3); if (q < best0) { best0 = q; bi0 = k0 + 3; }
        q = __fadd_rn(__fsub_rn(sqz1, __fmul_rn(2.f, c0)), n0); if (q < best1) { best1 = q; bi1 = k0; }
        q = __fadd_rn(__fsub_rn(sqz1, __fmul_rn(2.f, c1)), n1); if (q < best1) { best1 = q; bi1 = k0 + 1; }
        q = __fadd_rn(__fsub_rn(sqz1, __fmul_rn(2.f, c2)), n2); if (q < best1) { best1 = q; bi1 = k0 + 2; }
        q = __fadd_rn(__fsub_rn(sqz1, __fmul_rn(2.f, c3)), n3); if (q < best1) { best1 = q; bi1 = k0 + 3; }
    }
    float* zqp = zq + n * 262144 + y * 64 + x0;
    float* dp = g_dec + n * 262144 + y * 64 + x0;
#pragma unroll
    for (int c = 0; c < 64; c++) {
        float e0 = se[c * 512 + bi0];
        float e1 = se[c * 512 + bi1];
        *(float2*)(zqp + c * 4096) = make_float2(e0, e1);
        float d0 = __fadd_rn(z0[c], __fsub_rn(e0, z0[c]));
        float d1 = __fadd_rn(z1[c], __fsub_rn(e1, z1[c]));
        *(float2*)(dp + c * 4096) = make_float2(d0, d1);
    }
}

// ===========================================================================
// DECODER (1e-3 tolerance — register-tiled, order-free)
// ===========================================================================

// d1: conv_t 64->32, k3 s1 p1 == conv with flipped/swapped weights.
// g_dec -> g_d1(64,32,64,64). 256 thr = 4 og(8oc) x 32 r x 2 h; tile 32y x 16x.
#define D1_PITCH 19
#define D1_IN_FLOATS (64 * 34 * D1_PITCH)   // 41344
#define D1_W_FLOATS  (3 * 64 * 32)          // 6144
#define D1_SMEM_B   ((D1_IN_FLOATS + D1_W_FLOATS) * 4)
__global__ __launch_bounds__(256, 1) void k_d1(const float* __restrict__ w,
                                               const float* __restrict__ b) {
    extern __shared__ float sm[];
    float* sIn = sm;                 // [ci][34][19]
    float* sw  = sm + D1_IN_FLOATS;  // [kx][ci][o32]
    int tid = threadIdx.x;
    int og4 = tid >> 6;              // 0..3
    int sp = tid & 63;
    int r = sp >> 1, h = sp & 1;
    int t_y = blockIdx.x >> 2, t_x = blockIdx.x & 3;
    int n = blockIdx.y;
    int iy0 = 32 * t_y - 1, ix0 = 16 * t_x - 1;
    for (int idx = tid; idx < 64 * 34 * 18; idx += 256) {
        int ci = idx / 612, rr = idx - ci * 612;
        int iy = rr / 18, ix = rr - iy * 18;
        int gy = iy0 + iy, gx = ix0 + ix;
        float v = 0.f;
        if (gy >= 0 && gy < 64 && gx >= 0 && gx < 64)
            v = g_dec[((n * 64 + ci) * 64 + gy) * 64 + gx];
        sIn[ci * (34 * D1_PITCH) + iy * D1_PITCH + ix] = v;
    }
    float acc[64];
#pragma unroll
    for (int i = 0; i < 64; i++) acc[i] = 0.f;
#pragma unroll
    for (int ky = 0; ky < 3; ky++) {
        __syncthreads();
        for (int idx = tid; idx < D1_W_FLOATS; idx += 256) {
            int kx = idx >> 11, ci = (idx >> 5) & 63, o = idx & 31;
            sw[idx] = w[(ci * 32 + o) * 9 + (8 - ky * 3 - kx)];  // flip
        }
        __syncthreads();
#pragma unroll
        for (int kx = 0; kx < 3; kx++) {
            for (int ci = 0; ci < 64; ci++) {
                const float* vb = &sIn[ci * (34 * D1_PITCH) + (r + ky) * D1_PITCH + 8 * h + kx];
                float v[8];
#pragma unroll
                for (int j = 0; j < 8; j++) v[j] = vb[j];
                const float4* wp = (const float4*)&sw[(kx * 64 + ci) * 32 + og4 * 8];
                float4 w0 = wp[0], w1 = wp[1];
                float wv[8] = {w0.x, w0.y, w0.z, w0.w, w1.x, w1.y, w1.z, w1.w};
#pragma unroll
                for (int j = 0; j < 8; j++)
#pragma unroll
                    for (int oo = 0; oo < 8; oo++)
                        acc[j * 8 + oo] = fmaf(v[j], wv[oo], acc[j * 8 + oo]);
            }
        }
    }
    int oy = 32 * t_y + r, ox0 = 16 * t_x + 8 * h;
#pragma unroll
    for (int oo = 0; oo < 8; oo++) {
        int o = og4 * 8 + oo;
        float bb = b[o];
        float* op = g_d1 + ((n * 32 + o) * 64 + oy) * 64 + ox0;
#pragma unroll
        for (int j = 0; j < 8; j++)
            op[j] = fmaxf(acc[j * 8 + oo] + bb, 0.f);
    }
}

// d2: conv_t 32->64, k4 s2 p1. g_d1 -> g_d2(64,64,128,128).
// 256 thr = 8 og(8oc) x 16 r x 2 parity; thread = 8 same-parity x, 8 oc.
// Tile 16y x 16x out; input 10x10; full weight tile (32 KB fl) in smem.
#define D2_IN_FLOATS (32 * 10 * 11)     // 3520
#define D2_W_FLOATS  (16 * 32 * 64)     // 32768
#define D2_SMEM_B   ((D2_IN_FLOATS + D2_W_FLOATS) * 4)
__global__ __launch_bounds__(256, 1) void k_d2(const float* __restrict__ w,
                                               const float* __restrict__ b) {
    extern __shared__ float sm[];
    float* sIn = sm;                 // [ci][10][11]
    float* sw  = sm + D2_IN_FLOATS;  // [tap16][ci32][o64]
    int tid = threadIdx.x;
    int og = tid >> 5;               // 0..7
    int sp = tid & 31;
    int r = sp >> 1, h = sp & 1;
    int t_y = blockIdx.x >> 3, t_x = blockIdx.x & 7;
    int n = blockIdx.y;
    int iy0 = 8 * t_y - 1, ix0 = 8 * t_x - 1;
    for (int idx = tid; idx < 3200; idx += 256) {
        int ci = idx / 100, rr = idx - ci * 100;
        int iy = rr / 10, ix = rr - iy * 10;
        int gy = iy0 + iy, gx = ix0 + ix;
        float v = 0.f;
        if (gy >= 0 && gy < 64 && gx >= 0 && gx < 64)
            v = g_d1[((n * 32 + ci) * 64 + gy) * 64 + gx];
        sIn[ci * 110 + iy * 11 + ix] = v;
    }
    for (int idx = tid; idx < D2_W_FLOATS; idx += 256) {
        int tap = idx >> 11, ci = (idx >> 6) & 31, o = idx & 63;
        sw[idx] = w[(ci * 64 + o) * 16 + tap];
    }
    __syncthreads();
    int y = 16 * t_y + r;
    int py = (r + 1) & 1;
    int px = 1 - h;
    int iya = ((r + 1) >> 1) + 1;
    float acc[64];
#pragma unroll
    for (int i = 0; i < 64; i++) acc[i] = 0.f;
    for (int ci = 0; ci < 32; ci++) {
        float va[9], vb[9];
        const float* pa = &sIn[ci * 110 + iya * 11 + h];
        const float* pb = pa - 11;
#pragma unroll
        for (int i = 0; i < 9; i++) { va[i] = pa[i]; vb[i] = pb[i]; }
#pragma unroll
        for (int tky = 0; tky < 2; tky++) {
#pragma unroll
            for (int tkx = 0; tkx < 2; tkx++) {
                int tap = (py + 2 * tky) * 4 + (px + 2 * tkx);
                const float4* wp = (const float4*)&sw[tap * 2048 + ci * 64 + og * 8];
                float4 w0 = wp[0], w1 = wp[1];
                float wv[8] = {w0.x, w0.y, w0.z, w0.w, w1.x, w1.y, w1.z, w1.w};
#pragma unroll
                for (int j = 0; j < 8; j++) {
                    float v = tky ? vb[j + 1 - tkx] : va[j + 1 - tkx];
#pragma unroll
                    for (int oo = 0; oo < 8; oo++)
                        acc[j * 8 + oo] = fmaf(v, wv[oo], acc[j * 8 + oo]);
                }
            }
        }
    }
    float* opb = g_d2 + ((n * 64 + og * 8) * 128 + y) * 128 + 16 * t_x + h;
#pragma unroll
    for (int oo = 0; oo < 8; oo++) {
        float bb = b[og * 8 + oo];
        float* op = opb + oo * 16384;
#pragma unroll
        for (int j = 0; j < 8; j++)
            op[2 * j] = fmaxf(acc[j * 8 + oo] + bb, 0.f);
    }
}

// d3: conv_t 64->1, k4 s2 p1 -> x_hat
__global__ __launch_bounds__(256) void k_d3(const float* __restrict__ w,
                                            const float* __restrict__ b,
                                            float* __restrict__ xh) {
    __shared__ float sIn[6400];
    __shared__ float sw[1024];
    int tid = threadIdx.x;
    int sy = tid >> 4, sx = tid & 15;
    int tb = blockIdx.x;
    int tx = tb & 15, ty = tb >> 4;
    int n = blockIdx.y;
    int iy0 = 8 * ty - 1, ix0 = 8 * tx - 1;
    for (int e = tid; e < 6400; e += 256) {
        int ci = e / 100, r = e - ci * 100;
        int iy = r / 10, ix = r - iy * 10;
        int gy = iy0 + iy, gx = ix0 + ix;
        float v = 0.f;
        if (gy >= 0 && gy < 128 && gx >= 0 && gx < 128)
            v = g_d2[((n * 64 + ci) * 128 + gy) * 128 + gx];
        sIn[e] = v;
    }
    for (int e = tid; e < 1024; e += 256) sw[e] = w[e];
    __syncthreads();
    int y = 16 * ty + sy, x = 16 * tx + sx;
    int py = (y + 1) & 1, px = (x + 1) & 1;
    int iya = ((sy + 1 - py) >> 1) + 1, ixa = ((sx + 1 - px) >> 1) + 1;
    float acc = b[0];
#pragma unroll 8
    for (int ci = 0; ci < 64; ci++) {
#pragma unroll
        for (int t_y = 0; t_y < 2; t_y++) {
            int ky = py + 2 * t_y, iyl = iya - t_y;
#pragma unroll
            for (int t_x = 0; t_x < 2; t_x++) {
                int kx = px + 2 * t_x, ixl = ixa - t_x;
                acc = fmaf(sIn[ci * 100 + iyl * 10 + ixl], sw[ci * 16 + ky * 4 + kx], acc);
            }
        }
    }
    xh[n * 65536 + y * 256 + x] = acc;
}

// ---------------------------------------------------------------------------
extern "C" void kernel_launch(void* const* d_in, const int* in_sizes, int n_in,
                              void* d_out, int out_size) {
    const float* x   = (const float*)d_in[0];
    const float* e1w = (const float*)d_in[1];
    const float* e1b = (const float*)d_in[2];
    const float* e2w = (const float*)d_in[3];
    const float* e2b = (const float*)d_in[4];
    const float* e3w = (const float*)d_in[5];
    const float* e3b = (const float*)d_in[6];
    const float* emb = (const float*)d_in[7];
    const float* d1w = (const float*)d_in[8];
    const float* d1b = (const float*)d_in[9];
    const float* d2w = (const float*)d_in[10];
    const float* d2b = (const float*)d_in[11];
    const float* d3w = (const float*)d_in[12];
    const float* d3b = (const float*)d_in[13];
    float* out = (float*)d_out;
    float* ze = out + OFF_ZE;
    float* zq = out + OFF_ZQ;

    cudaFuncSetAttribute(k_e2, cudaFuncAttributeMaxDynamicSharedMemorySize, E2_SMEM_B);
    cudaFuncSetAttribute(k_e3, cudaFuncAttributeMaxDynamicSharedMemorySize, E3_SMEM_B);
    cudaFuncSetAttribute(k_vq, cudaFuncAttributeMaxDynamicSharedMemorySize, VQ_SMEM_B);
    cudaFuncSetAttribute(k_d1, cudaFuncAttributeMaxDynamicSharedMemorySize, D1_SMEM_B);
    cudaFuncSetAttribute(k_d2, cudaFuncAttributeMaxDynamicSharedMemorySize, D2_SMEM_B);

    k_e1<<<4096, 256>>>(x, e1w, e1b);
    k_e2<<<dim3(16, 64), 256, E2_SMEM_B>>>(e2w, e2b);
    k_e3<<<dim3(16, 64), 256, E3_SMEM_B>>>(e3w, e3b, ze);
    k_vq<<<512, 256, VQ_SMEM_B>>>(ze, emb, zq);
    k_d1<<<dim3(8, 64), 256, D1_SMEM_B>>>(d1w, d1b);
    k_d2<<<dim3(64, 64), 256, D2_SMEM_B>>>(d2w, d2b);
    k_d3<<<dim3(256, 64), 256>>>(d3w, d3b, out);
}

// round 7
// speedup vs baseline: 1.7366x; 1.7366x over previous
#include <cuda_runtime.h>

// Output layout: x_hat (64*1*256*256) | ze (64*64*64*64) | zq (64*64*64*64)
#define OFF_ZE 4194304
#define OFF_ZQ 20971520

// Scratch (__device__ globals)
__device__ float g_h1[33554432];   // (64,32,128,128)
__device__ float g_h2[16777216];   // (64,64,64,64)
__device__ float g_dec[16777216];  // (64,64,64,64)
__device__ float g_d1[8388608];    // (64,32,64,64)
__device__ float g_d2[67108864];   // (64,64,128,128)

// ===========================================================================
// ENCODER — bit-exact emulation of XLA-CPU/Eigen conv (FROZEN arithmetic)
// ===========================================================================

// e1: conv 1->32, k4 s2 p1. x(64,1,256,256) -> g_h1(64,32,128,128)
__global__ __launch_bounds__(256) void k_e1(const float* __restrict__ x,
                                            const float* __restrict__ w,
                                            const float* __restrict__ b) {
    __shared__ float sw[16][32];   // [tap][o]
    __shared__ float sb[32];
    int t = threadIdx.x;
    {
        int o = t & 31, tap = t >> 5;
        sw[tap][o] = w[o * 16 + tap];
        int e = t + 256; o = e & 31; tap = e >> 5;
        sw[tap][o] = w[o * 16 + tap];
    }
    if (t < 32) sb[t] = b[t];
    __syncthreads();
    int gid = blockIdx.x * 256 + t;
    int ox = gid & 127, oy = (gid >> 7) & 127, n = gid >> 14;
    float acc[32];
#pragma unroll
    for (int o = 0; o < 32; o++) acc[o] = 0.f;
    const float* xin = x + n * 65536;
#pragma unroll
    for (int ky = 0; ky < 4; ky++) {
        int iy = 2 * oy - 1 + ky;
        if (iy < 0 || iy >= 256) continue;
#pragma unroll
        for (int kx = 0; kx < 4; kx++) {
            int ix = 2 * ox - 1 + kx;
            if (ix < 0 || ix >= 256) continue;
            float v = xin[iy * 256 + ix];
#pragma unroll
            for (int o = 0; o < 32; o++) acc[o] = fmaf(v, sw[ky * 4 + kx][o], acc[o]);
        }
    }
    float* op = g_h1 + n * 524288 + oy * 128 + ox;
#pragma unroll
    for (int o = 0; o < 32; o++) op[o * 16384] = fmaxf(__fadd_rn(acc[o], sb[o]), 0.f);
}

// e2: conv 32->64, k4 s2 p1. g_h1 -> g_h2(64,64,64,64)
#define E2_PITCH 35
#define E2_IN_FLOATS (32 * 34 * E2_PITCH)
#define E2_W_FLOATS  (4 * 32 * 64)
#define E2_SMEM_B   ((E2_IN_FLOATS + E2_W_FLOATS) * 4)
__global__ __launch_bounds__(256, 1) void k_e2(const float* __restrict__ w,
                                               const float* __restrict__ b) {
    extern __shared__ float sm[];
    float* sIn = sm;                 // [ci][34][35]
    float* sw  = sm + E2_IN_FLOATS;  // [kx][ci][o]
    int tid = threadIdx.x;
    int og8 = tid >> 5;
    int sp = tid & 31;
    int r = sp >> 1, h = sp & 1;
    int t_y = blockIdx.x >> 2, t_x = blockIdx.x & 3;
    int n = blockIdx.y;
    int iy0 = 32 * t_y - 1, ix0 = 32 * t_x - 1;
    for (int idx = tid; idx < 32 * 34 * 34; idx += 256) {
        int ci = idx / 1156, rr = idx - ci * 1156;
        int iy = rr / 34, ix = rr - iy * 34;
        int gy = iy0 + iy, gx = ix0 + ix;
        float v = 0.f;
        if (gy >= 0 && gy < 128 && gx >= 0 && gx < 128)
            v = g_h1[((n * 32 + ci) * 128 + gy) * 128 + gx];
        sIn[ci * (34 * E2_PITCH) + iy * E2_PITCH + ix] = v;
    }
    float acc[64];
#pragma unroll
    for (int i = 0; i < 64; i++) acc[i] = 0.f;
#pragma unroll
    for (int ky = 0; ky < 4; ky++) {
        __syncthreads();
        for (int idx = tid; idx < E2_W_FLOATS; idx += 256) {
            int kx = idx >> 11, ci = (idx >> 6) & 31, o = idx & 63;
            sw[idx] = w[(o * 32 + ci) * 16 + ky * 4 + kx];
        }
        __syncthreads();
#pragma unroll
        for (int kx = 0; kx < 4; kx++) {
            for (int ci = 0; ci < 32; ci++) {
                const float* vb = &sIn[ci * (34 * E2_PITCH) + (2 * r + ky) * E2_PITCH + 16 * h + kx];
                float v[8];
#pragma unroll
                for (int j = 0; j < 8; j++) v[j] = vb[2 * j];
                const float4* wp = (const float4*)&sw[(kx * 32 + ci) * 64 + og8 * 8];
                float4 w0 = wp[0], w1 = wp[1];
                float wv[8] = {w0.x, w0.y, w0.z, w0.w, w1.x, w1.y, w1.z, w1.w};
#pragma unroll
                for (int j = 0; j < 8; j++)
#pragma unroll
                    for (int oo = 0; oo < 8; oo++)
                        acc[j * 8 + oo] = fmaf(v[j], wv[oo], acc[j * 8 + oo]);
            }
        }
    }
    int oy = 16 * t_y + r, ox0 = 16 * t_x + 8 * h;
#pragma unroll
    for (int oo = 0; oo < 8; oo++) {
        int o = og8 * 8 + oo;
        float bb = b[o];
        float* op = g_h2 + ((n * 64 + o) * 64 + oy) * 64 + ox0;
#pragma unroll
        for (int j = 0; j < 8; j++)
            op[j] = fmaxf(__fadd_rn(acc[j * 8 + oo], bb), 0.f);
    }
}

// e3: conv 64->64, k3 s1 p1. g_h2 -> ze (d_out)
#define E3_PITCH 21
#define E3_IN_FLOATS (64 * 18 * E3_PITCH)
#define E3_W_FLOATS  (3 * 64 * 64)
#define E3_SMEM_B   ((E3_IN_FLOATS + E3_W_FLOATS) * 4)
__global__ __launch_bounds__(256, 1) void k_e3(const float* __restrict__ w,
                                               const float* __restrict__ b,
                                               float* __restrict__ ze) {
    extern __shared__ float sm[];
    float* sIn = sm;                 // [ci][18][21]
    float* sw  = sm + E3_IN_FLOATS;  // [kx][ci][o]
    int tid = threadIdx.x;
    int og8 = tid >> 5;
    int sp = tid & 31;
    int r = sp >> 1, h = sp & 1;
    int t_y = blockIdx.x >> 2, t_x = blockIdx.x & 3;
    int n = blockIdx.y;
    int iy0 = 16 * t_y - 1, ix0 = 16 * t_x - 1;
    for (int idx = tid; idx < 64 * 18 * 18; idx += 256) {
        int ci = idx / 324, rr = idx - ci * 324;
        int iy = rr / 18, ix = rr - iy * 18;
        int gy = iy0 + iy, gx = ix0 + ix;
        float v = 0.f;
        if (gy >= 0 && gy < 64 && gx >= 0 && gx < 64)
            v = g_h2[((n * 64 + ci) * 64 + gy) * 64 + gx];
        sIn[ci * (18 * E3_PITCH) + iy * E3_PITCH + ix] = v;
    }
    float acc[64];
#pragma unroll
    for (int i = 0; i < 64; i++) acc[i] = 0.f;
#pragma unroll
    for (int ky = 0; ky < 3; ky++) {
        __syncthreads();
        for (int idx = tid; idx < E3_W_FLOATS; idx += 256) {
            int kx = idx >> 12, ci = (idx >> 6) & 63, o = idx & 63;
            sw[idx] = w[(o * 64 + ci) * 9 + ky * 3 + kx];
        }
        __syncthreads();
#pragma unroll
        for (int kx = 0; kx < 3; kx++) {
            for (int ci = 0; ci < 64; ci++) {
                const float* vb = &sIn[ci * (18 * E3_PITCH) + (r + ky) * E3_PITCH + 8 * h + kx];
                float v[8];
#pragma unroll
                for (int j = 0; j < 8; j++) v[j] = vb[j];
                const float4* wp = (const float4*)&sw[(kx * 64 + ci) * 64 + og8 * 8];
                float4 w0 = wp[0], w1 = wp[1];
                float wv[8] = {w0.x, w0.y, w0.z, w0.w, w1.x, w1.y, w1.z, w1.w};
#pragma unroll
                for (int j = 0; j < 8; j++)
#pragma unroll
                    for (int oo = 0; oo < 8; oo++)
                        acc[j * 8 + oo] = fmaf(v[j], wv[oo], acc[j * 8 + oo]);
            }
        }
    }
    int oy = 16 * t_y + r, ox0 = 16 * t_x + 8 * h;
#pragma unroll
    for (int oo = 0; oo < 8; oo++) {
        int o = og8 * 8 + oo;
        float bb = b[o];
        float* op = ze + ((n * 64 + o) * 64 + oy) * 64 + ox0;
#pragma unroll
        for (int j = 0; j < 8; j++)
            op[j] = fmaxf(__fadd_rn(acc[j * 8 + oo], bb), 0.f);
    }
}

// ===========================================================================
// VQ — GEMM-tiled, FROZEN arithmetic chains.
// Block: 128 positions x 512 codes (4 chunks of 128). 256 thr = 16 pt x 16 kt.
// Thread: 8 pos x 8 codes; per c: 4 LDS.128 -> 64 FMA.
// Per (pos,code): dot = seq fmaf c=0..63 (chunk holds full c range).
// dist = add(sub(sqz, mul(2,dot)), sqe); argmin = global first-min via
// in-thread ascending-k strict < + cross-lane merge with idx tiebreak.
// ===========================================================================
#define VQ_ZP 132
#define VQ_Z_FL   (64 * VQ_ZP)         // 8448
#define VQ_E_FL   (64 * VQ_ZP)         // 8448
#define VQ_SMEM_FL (VQ_Z_FL + VQ_E_FL + 128 + 128 + 128)
#define VQ_SMEM_B (VQ_SMEM_FL * 4)
__global__ __launch_bounds__(256, 2) void k_vq(const float* __restrict__ ze,
                                               const float* __restrict__ emb,
                                               float* __restrict__ zq) {
    extern __shared__ float sm[];
    float* sz   = sm;                        // [c][pos] pitch 132
    float* se   = sm + VQ_Z_FL;              // [c][k]  pitch 132 (chunk)
    float* ssqz = sm + VQ_Z_FL + VQ_E_FL;    // [128]
    float* snc  = ssqz + 128;                // [128] chunk sqe
    int*   sbi  = (int*)(snc + 128);         // [128]
    int tid = threadIdx.x;
    int pt = tid >> 4;          // 0..15 -> positions pt*8..pt*8+7
    int kt = tid & 15;          // 0..15 -> codes kt*8..kt*8+7 (per chunk)

    int base = blockIdx.x * 128;             // flat position base (one n)
    int n = base >> 12;
    int rem = base & 4095;
    const float* zg = ze + n * 262144 + rem;

    // load z tile [c][pos]
    for (int idx = tid; idx < 8192; idx += 256) {
        int c = idx >> 7, pos = idx & 127;
        sz[c * VQ_ZP + pos] = zg[c * 4096 + pos];
    }
    __syncthreads();
    // sqz per position: seq c chain add(mul)
    if (tid < 128) {
        float s = 0.f;
#pragma unroll
        for (int c = 0; c < 64; c++) {
            float z = sz[c * VQ_ZP + tid];
            s = __fadd_rn(s, __fmul_rn(z, z));
        }
        ssqz[tid] = s;
    }

    float best[8], bi_f[8];
    int bi[8];
#pragma unroll
    for (int p = 0; p < 8; p++) { best[p] = 3.4028235e38f; bi[p] = 0; }
    (void)bi_f;

    for (int ch = 0; ch < 4; ch++) {
        int kc0 = ch * 128;
        __syncthreads();
        // load codebook chunk transposed: se[c][k]
        for (int idx = tid; idx < 8192; idx += 256) {
            int k = idx >> 6, c = idx & 63;
            se[c * VQ_ZP + k] = emb[(kc0 + k) * 64 + c];
        }
        __syncthreads();
        // chunk code norms: seq c chain add(mul)
        if (tid < 128) {
            float s = 0.f;
#pragma unroll
            for (int c = 0; c < 64; c++) {
                float e = se[c * VQ_ZP + tid];
                s = __fadd_rn(s, __fmul_rn(e, e));
            }
            snc[tid] = s;
        }
        // main GEMM microkernel: acc[p][j] over c=0..63 sequential
        float acc[64];
#pragma unroll
        for (int i = 0; i < 64; i++) acc[i] = 0.f;
        const float* zp = sz + pt * 8;
        const float* ep = se + kt * 8;
        for (int c = 0; c < 64; c++) {
            float4 z0 = *(const float4*)(zp + c * VQ_ZP);
            float4 z1 = *(const float4*)(zp + c * VQ_ZP + 4);
            float4 e0 = *(const float4*)(ep + c * VQ_ZP);
            float4 e1 = *(const float4*)(ep + c * VQ_ZP + 4);
            float zr[8] = {z0.x, z0.y, z0.z, z0.w, z1.x, z1.y, z1.z, z1.w};
            float er[8] = {e0.x, e0.y, e0.z, e0.w, e1.x, e1.y, e1.z, e1.w};
#pragma unroll
            for (int p = 0; p < 8; p++)
#pragma unroll
                for (int j = 0; j < 8; j++)
                    acc[p * 8 + j] = fmaf(zr[p], er[j], acc[p * 8 + j]);
        }
        __syncthreads();   // snc ready; also keeps se alive until here
        // distances + in-thread argmin (ascending j => ascending k)
#pragma unroll
        for (int p = 0; p < 8; p++) {
            float sq = ssqz[pt * 8 + p];
#pragma unroll
            for (int j = 0; j < 8; j++) {
                float q = __fadd_rn(__fsub_rn(sq, __fmul_rn(2.f, acc[p * 8 + j])),
                                    snc[kt * 8 + j]);
                int kidx = kc0 + kt * 8 + j;
                if (q < best[p]) { best[p] = q; bi[p] = kidx; }
            }
        }
    }
    // cross-lane merge over the 16 kt lanes (same warp, lanes pt*16.. grouped)
#pragma unroll
    for (int p = 0; p < 8; p++) {
        float bv = best[p];
        int ii = bi[p];
#pragma unroll
        for (int off = 1; off < 16; off <<= 1) {
            float ov = __shfl_xor_sync(0xffffffffu, bv, off);
            int oi = __shfl_xor_sync(0xffffffffu, ii, off);
            if (ov < bv || (ov == bv && oi < ii)) { bv = ov; ii = oi; }
        }
        if (kt == 0) sbi[pt * 8 + p] = ii;
    }
    __syncthreads();
    // epilogue: 2 threads per position (c halves)
    {
        int pos = tid & 127;
        int c0 = (tid >> 7) * 32;
        int code = sbi[pos];
        const float* eg = emb + code * 64;
        float* zqp = zq + n * 262144 + rem + pos;
        float* dp = g_dec + n * 262144 + rem + pos;
#pragma unroll
        for (int c = 0; c < 32; c++) {
            int cc = c0 + c;
            float e = __ldg(eg + cc);
            float z = sz[cc * VQ_ZP + pos];
            zqp[cc * 4096] = e;
            dp[cc * 4096] = __fadd_rn(z, __fsub_rn(e, z));
        }
    }
}

// ===========================================================================
// DECODER (1e-3 tolerance — R5 proven kernels)
// ===========================================================================

// d1: conv_t 64->32, k3 s1 p1 == conv with flipped/swapped weights
__global__ __launch_bounds__(256) void k_d1(const float* __restrict__ w,
                                            const float* __restrict__ b) {
    __shared__ float sIn[8 * 324];
    __shared__ float sw[2304];
    int tid = threadIdx.x;
    int sy = tid >> 4, sx = tid & 15;
    int tb = blockIdx.x;
    int tx = tb & 3, ty = tb >> 2;
    int n = blockIdx.y;
    int iy0 = 16 * ty - 1, ix0 = 16 * tx - 1;
    float acc[32];
#pragma unroll
    for (int o = 0; o < 32; o++) acc[o] = b[o];
    for (int cc = 0; cc < 8; cc++) {
        __syncthreads();
        for (int e = tid; e < 2592; e += 256) {
            int ci = e / 324, r = e - ci * 324;
            int iy = r / 18, ix = r - iy * 18;
            int gy = iy0 + iy, gx = ix0 + ix;
            float v = 0.f;
            if (gy >= 0 && gy < 64 && gx >= 0 && gx < 64)
                v = g_dec[((n * 64 + cc * 8 + ci) * 64 + gy) * 64 + gx];
            sIn[e] = v;
        }
        for (int e = tid; e < 2304; e += 256) {
            int ci = e / 288, r = e - ci * 288;
            int kk = r >> 5, o = r & 31;
            sw[e] = w[((cc * 8 + ci) * 32 + o) * 9 + (8 - kk)];
        }
        __syncthreads();
#pragma unroll
        for (int ci = 0; ci < 8; ci++) {
#pragma unroll
            for (int ky = 0; ky < 3; ky++) {
                const float* ip = &sIn[ci * 324 + (sy + ky) * 18 + sx];
#pragma unroll
                for (int kx = 0; kx < 3; kx++) {
                    float v = ip[kx];
                    const float* wp = &sw[(ci * 9 + ky * 3 + kx) * 32];
#pragma unroll
                    for (int o = 0; o < 32; o++) acc[o] = fmaf(v, wp[o], acc[o]);
                }
            }
        }
    }
    int oy = 16 * ty + sy, ox = 16 * tx + sx;
    float* op = g_d1 + n * 131072 + oy * 64 + ox;
#pragma unroll
    for (int o = 0; o < 32; o++) op[o * 4096] = fmaxf(acc[o], 0.f);
}

// d2: conv_t 32->64, k4 s2 p1
__global__ __launch_bounds__(512, 1) void k_d2(const float* __restrict__ w,
                                               const float* __restrict__ b) {
    __shared__ float sIn[3200];
    __shared__ float sw[8192];
    int tid = threadIdx.x;
    int og = tid >> 8;
    int s = tid & 255;
    int sy = s >> 4, sx = s & 15;
    int tb = blockIdx.x;
    int tx = tb & 7, ty = tb >> 3;
    int n = blockIdx.y;
    int iy0 = 8 * ty - 1, ix0 = 8 * tx - 1;
    for (int e = tid; e < 3200; e += 512) {
        int ci = e / 100, r = e - ci * 100;
        int iy = r / 10, ix = r - iy * 10;
        int gy = iy0 + iy, gx = ix0 + ix;
        float v = 0.f;
        if (gy >= 0 && gy < 64 && gx >= 0 && gx < 64)
            v = g_d1[((n * 32 + ci) * 64 + gy) * 64 + gx];
        sIn[e] = v;
    }
    float acc[32];
#pragma unroll
    for (int o = 0; o < 32; o++) acc[o] = b[og * 32 + o];
    int y = 16 * ty + sy, x = 16 * tx + sx;
    int py = (y + 1) & 1, px = (x + 1) & 1;
    int iya = ((sy + 1 - py) >> 1) + 1, ixa = ((sx + 1 - px) >> 1) + 1;
    for (int cc = 0; cc < 4; cc++) {
        __syncthreads();
        for (int e = tid; e < 8192; e += 512) {
            int ci = e >> 10, kk = (e >> 6) & 15, o = e & 63;
            sw[e] = w[((cc * 8 + ci) * 64 + o) * 16 + kk];
        }
        __syncthreads();
#pragma unroll
        for (int ci = 0; ci < 8; ci++) {
#pragma unroll
            for (int t_y = 0; t_y < 2; t_y++) {
                int ky = py + 2 * t_y, iyl = iya - t_y;
#pragma unroll
                for (int t_x = 0; t_x < 2; t_x++) {
                    int kx = px + 2 * t_x, ixl = ixa - t_x;
                    float v = sIn[(cc * 8 + ci) * 100 + iyl * 10 + ixl];
                    const float* wp = &sw[(ci * 16 + ky * 4 + kx) * 64 + og * 32];
#pragma unroll
                    for (int o = 0; o < 32; o++) acc[o] = fmaf(v, wp[o], acc[o]);
                }
            }
        }
    }
    float* op = g_d2 + n * 1048576 + (og * 32) * 16384 + y * 128 + x;
#pragma unroll
    for (int o = 0; o < 32; o++) op[o * 16384] = fmaxf(acc[o], 0.f);
}

// d3: conv_t 64->1, k4 s2 p1 -> x_hat
__global__ __launch_bounds__(256) void k_d3(const float* __restrict__ w,
                                            const float* __restrict__ b,
                                            float* __restrict__ xh) {
    __shared__ float sIn[6400];
    __shared__ float sw[1024];
    int tid = threadIdx.x;
    int sy = tid >> 4, sx = tid & 15;
    int tb = blockIdx.x;
    int tx = tb & 15, ty = tb >> 4;
    int n = blockIdx.y;
    int iy0 = 8 * ty - 1, ix0 = 8 * tx - 1;
    for (int e = tid; e < 6400; e += 256) {
        int ci = e / 100, r = e - ci * 100;
        int iy = r / 10, ix = r - iy * 10;
        int gy = iy0 + iy, gx = ix0 + ix;
        float v = 0.f;
        if (gy >= 0 && gy < 128 && gx >= 0 && gx < 128)
            v = g_d2[((n * 64 + ci) * 128 + gy) * 128 + gx];
        sIn[e] = v;
    }
    for (int e = tid; e < 1024; e += 256) sw[e] = w[e];
    __syncthreads();
    int y = 16 * ty + sy, x = 16 * tx + sx;
    int py = (y + 1) & 1, px = (x + 1) & 1;
    int iya = ((sy + 1 - py) >> 1) + 1, ixa = ((sx + 1 - px) >> 1) + 1;
    float acc = b[0];
#pragma unroll 8
    for (int ci = 0; ci < 64; ci++) {
#pragma unroll
        for (int t_y = 0; t_y < 2; t_y++) {
            int ky = py + 2 * t_y, iyl = iya - t_y;
#pragma unroll
            for (int t_x = 0; t_x < 2; t_x++) {
                int kx = px + 2 * t_x, ixl = ixa - t_x;
                acc = fmaf(sIn[ci * 100 + iyl * 10 + ixl], sw[ci * 16 + ky * 4 + kx], acc);
            }
        }
    }
    xh[n * 65536 + y * 256 + x] = acc;
}

// ---------------------------------------------------------------------------
extern "C" void kernel_launch(void* const* d_in, const int* in_sizes, int n_in,
                              void* d_out, int out_size) {
    const float* x   = (const float*)d_in[0];
    const float* e1w = (const float*)d_in[1];
    const float* e1b = (const float*)d_in[2];
    const float* e2w = (const float*)d_in[3];
    const float* e2b = (const float*)d_in[4];
    const float* e3w = (const float*)d_in[5];
    const float* e3b = (const float*)d_in[6];
    const float* emb = (const float*)d_in[7];
    const float* d1w = (const float*)d_in[8];
    const float* d1b = (const float*)d_in[9];
    const float* d2w = (const float*)d_in[10];
    const float* d2b = (const float*)d_in[11];
    const float* d3w = (const float*)d_in[12];
    const float* d3b = (const float*)d_in[13];
    float* out = (float*)d_out;
    float* ze = out + OFF_ZE;
    float* zq = out + OFF_ZQ;

    cudaFuncSetAttribute(k_e2, cudaFuncAttributeMaxDynamicSharedMemorySize, E2_SMEM_B);
    cudaFuncSetAttribute(k_e3, cudaFuncAttributeMaxDynamicSharedMemorySize, E3_SMEM_B);
    cudaFuncSetAttribute(k_vq, cudaFuncAttributeMaxDynamicSharedMemorySize, VQ_SMEM_B);

    k_e1<<<4096, 256>>>(x, e1w, e1b);
    k_e2<<<dim3(16, 64), 256, E2_SMEM_B>>>(e2w, e2b);
    k_e3<<<dim3(16, 64), 256, E3_SMEM_B>>>(e3w, e3b, ze);
    k_vq<<<2048, 256, VQ_SMEM_B>>>(ze, emb, zq);
    k_d1<<<dim3(16, 64), 256>>>(d1w, d1b);
    k_d2<<<dim3(64, 64), 512>>>(d2w, d2b);
    k_d3<<<dim3(256, 64), 256>>>(d3w, d3b, out);
}

// round 10
// speedup vs baseline: 2.1423x; 1.2336x over previous
#include <cuda_runtime.h>

// Output layout: x_hat (64*1*256*256) | ze (64*64*64*64) | zq (64*64*64*64)
#define OFF_ZE 4194304
#define OFF_ZQ 20971520

// Scratch (__device__ globals)
__device__ float g_h1[33554432];   // (64,32,128,128)
__device__ float g_h2[16777216];   // (64,64,64,64)
__device__ float g_dec[16777216];  // (64,64,64,64)
__device__ float g_d1[8388608];    // (64,32,64,64)
__device__ float g_d2[67108864];   // (64,64,128,128)

// ===========================================================================
// ENCODER — bit-exact emulation of XLA-CPU/Eigen conv (FROZEN arithmetic)
// ===========================================================================

// e1: conv 1->32, k4 s2 p1. x(64,1,256,256) -> g_h1(64,32,128,128)
__global__ __launch_bounds__(256) void k_e1(const float* __restrict__ x,
                                            const float* __restrict__ w,
                                            const float* __restrict__ b) {
    __shared__ float sw[16][32];   // [tap][o]
    __shared__ float sb[32];
    int t = threadIdx.x;
    {
        int o = t & 31, tap = t >> 5;
        sw[tap][o] = w[o * 16 + tap];
        int e = t + 256; o = e & 31; tap = e >> 5;
        sw[tap][o] = w[o * 16 + tap];
    }
    if (t < 32) sb[t] = b[t];
    __syncthreads();
    int gid = blockIdx.x * 256 + t;
    int ox = gid & 127, oy = (gid >> 7) & 127, n = gid >> 14;
    float acc[32];
#pragma unroll
    for (int o = 0; o < 32; o++) acc[o] = 0.f;
    const float* xin = x + n * 65536;
#pragma unroll
    for (int ky = 0; ky < 4; ky++) {
        int iy = 2 * oy - 1 + ky;
        if (iy < 0 || iy >= 256) continue;
#pragma unroll
        for (int kx = 0; kx < 4; kx++) {
            int ix = 2 * ox - 1 + kx;
            if (ix < 0 || ix >= 256) continue;
            float v = xin[iy * 256 + ix];
#pragma unroll
            for (int o = 0; o < 32; o++) acc[o] = fmaf(v, sw[ky * 4 + kx][o], acc[o]);
        }
    }
    float* op = g_h1 + n * 524288 + oy * 128 + ox;
#pragma unroll
    for (int o = 0; o < 32; o++) op[o * 16384] = fmaxf(__fadd_rn(acc[o], sb[o]), 0.f);
}

// e2: conv 32->64, k4 s2 p1. g_h1 -> g_h2(64,64,64,64)
#define E2_PITCH 35
#define E2_IN_FLOATS (32 * 34 * E2_PITCH)
#define E2_W_FLOATS  (4 * 32 * 64)
#define E2_SMEM_B   ((E2_IN_FLOATS + E2_W_FLOATS) * 4)
__global__ __launch_bounds__(256, 1) void k_e2(const float* __restrict__ w,
                                               const float* __restrict__ b) {
    extern __shared__ float sm[];
    float* sIn = sm;                 // [ci][34][35]
    float* sw  = sm + E2_IN_FLOATS;  // [kx][ci][o]
    int tid = threadIdx.x;
    int og8 = tid >> 5;
    int sp = tid & 31;
    int r = sp >> 1, h = sp & 1;
    int t_y = blockIdx.x >> 2, t_x = blockIdx.x & 3;
    int n = blockIdx.y;
    int iy0 = 32 * t_y - 1, ix0 = 32 * t_x - 1;
    for (int idx = tid; idx < 32 * 34 * 34; idx += 256) {
        int ci = idx / 1156, rr = idx - ci * 1156;
        int iy = rr / 34, ix = rr - iy * 34;
        int gy = iy0 + iy, gx = ix0 + ix;
        float v = 0.f;
        if (gy >= 0 && gy < 128 && gx >= 0 && gx < 128)
            v = g_h1[((n * 32 + ci) * 128 + gy) * 128 + gx];
        sIn[ci * (34 * E2_PITCH) + iy * E2_PITCH + ix] = v;
    }
    float acc[64];
#pragma unroll
    for (int i = 0; i < 64; i++) acc[i] = 0.f;
#pragma unroll
    for (int ky = 0; ky < 4; ky++) {
        __syncthreads();
        for (int idx = tid; idx < E2_W_FLOATS; idx += 256) {
            int kx = idx >> 11, ci = (idx >> 6) & 31, o = idx & 63;
            sw[idx] = w[(o * 32 + ci) * 16 + ky * 4 + kx];
        }
        __syncthreads();
#pragma unroll
        for (int kx = 0; kx < 4; kx++) {
            for (int ci = 0; ci < 32; ci++) {
                const float* vb = &sIn[ci * (34 * E2_PITCH) + (2 * r + ky) * E2_PITCH + 16 * h + kx];
                float v[8];
#pragma unroll
                for (int j = 0; j < 8; j++) v[j] = vb[2 * j];
                const float4* wp = (const float4*)&sw[(kx * 32 + ci) * 64 + og8 * 8];
                float4 w0 = wp[0], w1 = wp[1];
                float wv[8] = {w0.x, w0.y, w0.z, w0.w, w1.x, w1.y, w1.z, w1.w};
#pragma unroll
                for (int j = 0; j < 8; j++)
#pragma unroll
                    for (int oo = 0; oo < 8; oo++)
                        acc[j * 8 + oo] = fmaf(v[j], wv[oo], acc[j * 8 + oo]);
            }
        }
    }
    int oy = 16 * t_y + r, ox0 = 16 * t_x + 8 * h;
#pragma unroll
    for (int oo = 0; oo < 8; oo++) {
        int o = og8 * 8 + oo;
        float bb = b[o];
        float* op = g_h2 + ((n * 64 + o) * 64 + oy) * 64 + ox0;
#pragma unroll
        for (int j = 0; j < 8; j++)
            op[j] = fmaxf(__fadd_rn(acc[j * 8 + oo], bb), 0.f);
    }
}

// e3: conv 64->64, k3 s1 p1. g_h2 -> ze (d_out)
#define E3_PITCH 21
#define E3_IN_FLOATS (64 * 18 * E3_PITCH)
#define E3_W_FLOATS  (3 * 64 * 64)
#define E3_SMEM_B   ((E3_IN_FLOATS + E3_W_FLOATS) * 4)
__global__ __launch_bounds__(256, 1) void k_e3(const float* __restrict__ w,
                                               const float* __restrict__ b,
                                               float* __restrict__ ze) {
    extern __shared__ float sm[];
    float* sIn = sm;                 // [ci][18][21]
    float* sw  = sm + E3_IN_FLOATS;  // [kx][ci][o]
    int tid = threadIdx.x;
    int og8 = tid >> 5;
    int sp = tid & 31;
    int r = sp >> 1, h = sp & 1;
    int t_y = blockIdx.x >> 2, t_x = blockIdx.x & 3;
    int n = blockIdx.y;
    int iy0 = 16 * t_y - 1, ix0 = 16 * t_x - 1;
    for (int idx = tid; idx < 64 * 18 * 18; idx += 256) {
        int ci = idx / 324, rr = idx - ci * 324;
        int iy = rr / 18, ix = rr - iy * 18;
        int gy = iy0 + iy, gx = ix0 + ix;
        float v = 0.f;
        if (gy >= 0 && gy < 64 && gx >= 0 && gx < 64)
            v = g_h2[((n * 64 + ci) * 64 + gy) * 64 + gx];
        sIn[ci * (18 * E3_PITCH) + iy * E3_PITCH + ix] = v;
    }
    float acc[64];
#pragma unroll
    for (int i = 0; i < 64; i++) acc[i] = 0.f;
#pragma unroll
    for (int ky = 0; ky < 3; ky++) {
        __syncthreads();
        for (int idx = tid; idx < E3_W_FLOATS; idx += 256) {
            int kx = idx >> 12, ci = (idx >> 6) & 63, o = idx & 63;
            sw[idx] = w[(o * 64 + ci) * 9 + ky * 3 + kx];
        }
        __syncthreads();
#pragma unroll
        for (int kx = 0; kx < 3; kx++) {
            for (int ci = 0; ci < 64; ci++) {
                const float* vb = &sIn[ci * (18 * E3_PITCH) + (r + ky) * E3_PITCH + 8 * h + kx];
                float v[8];
#pragma unroll
                for (int j = 0; j < 8; j++) v[j] = vb[j];
                const float4* wp = (const float4*)&sw[(kx * 64 + ci) * 64 + og8 * 8];
                float4 w0 = wp[0], w1 = wp[1];
                float wv[8] = {w0.x, w0.y, w0.z, w0.w, w1.x, w1.y, w1.z, w1.w};
#pragma unroll
                for (int j = 0; j < 8; j++)
#pragma unroll
                    for (int oo = 0; oo < 8; oo++)
                        acc[j * 8 + oo] = fmaf(v[j], wv[oo], acc[j * 8 + oo]);
            }
        }
    }
    int oy = 16 * t_y + r, ox0 = 16 * t_x + 8 * h;
#pragma unroll
    for (int oo = 0; oo < 8; oo++) {
        int o = og8 * 8 + oo;
        float bb = b[o];
        float* op = ze + ((n * 64 + o) * 64 + oy) * 64 + ox0;
#pragma unroll
        for (int j = 0; j < 8; j++)
            op[j] = fmaxf(__fadd_rn(acc[j * 8 + oo], bb), 0.f);
    }
}

// ===========================================================================
// VQ — GEMM-tiled, FROZEN arithmetic chains (R7, near FMA floor)
// ===========================================================================
#define VQ_ZP 132
#define VQ_Z_FL   (64 * VQ_ZP)
#define VQ_E_FL   (64 * VQ_ZP)
#define VQ_SMEM_FL (VQ_Z_FL + VQ_E_FL + 128 + 128 + 128)
#define VQ_SMEM_B (VQ_SMEM_FL * 4)
__global__ __launch_bounds__(256, 2) void k_vq(const float* __restrict__ ze,
                                               const float* __restrict__ emb,
                                               float* __restrict__ zq) {
    extern __shared__ float sm[];
    float* sz   = sm;
    float* se   = sm + VQ_Z_FL;
    float* ssqz = sm + VQ_Z_FL + VQ_E_FL;
    float* snc  = ssqz + 128;
    int*   sbi  = (int*)(snc + 128);
    int tid = threadIdx.x;
    int pt = tid >> 4;
    int kt = tid & 15;

    int base = blockIdx.x * 128;
    int n = base >> 12;
    int rem = base & 4095;
    const float* zg = ze + n * 262144 + rem;

    for (int idx = tid; idx < 8192; idx += 256) {
        int c = idx >> 7, pos = idx & 127;
        sz[c * VQ_ZP + pos] = zg[c * 4096 + pos];
    }
    __syncthreads();
    if (tid < 128) {
        float s = 0.f;
#pragma unroll
        for (int c = 0; c < 64; c++) {
            float z = sz[c * VQ_ZP + tid];
            s = __fadd_rn(s, __fmul_rn(z, z));
        }
        ssqz[tid] = s;
    }

    float best[8];
    int bi[8];
#pragma unroll
    for (int p = 0; p < 8; p++) { best[p] = 3.4028235e38f; bi[p] = 0; }

    for (int ch = 0; ch < 4; ch++) {
        int kc0 = ch * 128;
        __syncthreads();
        for (int idx = tid; idx < 8192; idx += 256) {
            int k = idx >> 6, c = idx & 63;
            se[c * VQ_ZP + k] = emb[(kc0 + k) * 64 + c];
        }
        __syncthreads();
        if (tid < 128) {
            float s = 0.f;
#pragma unroll
            for (int c = 0; c < 64; c++) {
                float e = se[c * VQ_ZP + tid];
                s = __fadd_rn(s, __fmul_rn(e, e));
            }
            snc[tid] = s;
        }
        float acc[64];
#pragma unroll
        for (int i = 0; i < 64; i++) acc[i] = 0.f;
        const float* zp = sz + pt * 8;
        const float* ep = se + kt * 8;
        for (int c = 0; c < 64; c++) {
            float4 z0 = *(const float4*)(zp + c * VQ_ZP);
            float4 z1 = *(const float4*)(zp + c * VQ_ZP + 4);
            float4 e0 = *(const float4*)(ep + c * VQ_ZP);
            float4 e1 = *(const float4*)(ep + c * VQ_ZP + 4);
            float zr[8] = {z0.x, z0.y, z0.z, z0.w, z1.x, z1.y, z1.z, z1.w};
            float er[8] = {e0.x, e0.y, e0.z, e0.w, e1.x, e1.y, e1.z, e1.w};
#pragma unroll
            for (int p = 0; p < 8; p++)
#pragma unroll
                for (int j = 0; j < 8; j++)
                    acc[p * 8 + j] = fmaf(zr[p], er[j], acc[p * 8 + j]);
        }
        __syncthreads();
#pragma unroll
        for (int p = 0; p < 8; p++) {
            float sq = ssqz[pt * 8 + p];
#pragma unroll
            for (int j = 0; j < 8; j++) {
                float q = __fadd_rn(__fsub_rn(sq, __fmul_rn(2.f, acc[p * 8 + j])),
                                    snc[kt * 8 + j]);
                int kidx = kc0 + kt * 8 + j;
                if (q < best[p]) { best[p] = q; bi[p] = kidx; }
            }
        }
    }
#pragma unroll
    for (int p = 0; p < 8; p++) {
        float bv = best[p];
        int ii = bi[p];
#pragma unroll
        for (int off = 1; off < 16; off <<= 1) {
            float ov = __shfl_xor_sync(0xffffffffu, bv, off);
            int oi = __shfl_xor_sync(0xffffffffu, ii, off);
            if (ov < bv || (ov == bv && oi < ii)) { bv = ov; ii = oi; }
        }
        if (kt == 0) sbi[pt * 8 + p] = ii;
    }
    __syncthreads();
    {
        int pos = tid & 127;
        int c0 = (tid >> 7) * 32;
        int code = sbi[pos];
        const float* eg = emb + code * 64;
        float* zqp = zq + n * 262144 + rem + pos;
        float* dp = g_dec + n * 262144 + rem + pos;
#pragma unroll
        for (int c = 0; c < 32; c++) {
            int cc = c0 + c;
            float e = __ldg(eg + cc);
            float z = sz[cc * VQ_ZP + pos];
            zqp[cc * 4096] = e;
            dp[cc * 4096] = __fadd_rn(z, __fsub_rn(e, z));
        }
    }
}

// ===========================================================================
// DECODER (1e-3 tolerance — order-free, register-tiled, >=2 CTAs/SM)
// ===========================================================================

// d1: conv_t 64->32, k3 s1 p1 == conv with flipped/swapped weights.
// g_dec -> g_d1(64,32,64,64). Block: 32y x 16x out tile, all 32 oc.
// 256 thr = 64 pos-groups(8) x 4 oc-groups(8). ci chunked by 16 (order-free).
#define D1_CI 16
#define D1_IN_FL (D1_CI * 34 * 19)    // 10336
#define D1_W_FL  (D1_CI * 9 * 32)     // 4608
#define D1_SMEM_B ((D1_IN_FL + D1_W_FL) * 4)
__global__ __launch_bounds__(256, 2) void k_d1(const float* __restrict__ w,
                                               const float* __restrict__ b) {
    extern __shared__ float sm[];
    float* sIn = sm;             // [ci][34][19]
    float* sw  = sm + D1_IN_FL;  // [ci][tap9][o32] flipped
    int tid = threadIdx.x;
    int kt = tid & 3;            // oc group: kt*8..kt*8+7
    int pt = tid >> 2;           // 0..63
    int r = pt >> 1, h = pt & 1;
    int ty = blockIdx.x >> 2, tx = blockIdx.x & 3;
    int n = blockIdx.y;
    int iy0 = 32 * ty - 1, ix0 = 16 * tx - 1;
    float acc[64];
#pragma unroll
    for (int i = 0; i < 64; i++) acc[i] = 0.f;
    for (int cc = 0; cc < 4; cc++) {
        int ci0 = cc * D1_CI;
        __syncthreads();
        for (int idx = tid; idx < D1_CI * 34 * 18; idx += 256) {
            int ci = idx / 612, rr = idx - ci * 612;
            int iy = rr / 18, ix = rr - iy * 18;
            int gy = iy0 + iy, gx = ix0 + ix;
            float v = 0.f;
            if (gy >= 0 && gy < 64 && gx >= 0 && gx < 64)
                v = g_dec[((n * 64 + ci0 + ci) * 64 + gy) * 64 + gx];
            sIn[ci * 646 + iy * 19 + ix] = v;
        }
        for (int idx = tid; idx < D1_W_FL; idx += 256) {
            int ci = idx / 288, rr = idx - ci * 288;
            int tap = rr >> 5, o = rr & 31;
            sw[(ci * 9 + tap) * 32 + o] = w[((ci0 + ci) * 32 + o) * 9 + (8 - tap)];
        }
        __syncthreads();
#pragma unroll 4
        for (int ci = 0; ci < D1_CI; ci++) {
#pragma unroll
            for (int ky = 0; ky < 3; ky++) {
                const float* vp = &sIn[ci * 646 + (r + ky) * 19 + 8 * h];
                float v[10];
#pragma unroll
                for (int i = 0; i < 10; i++) v[i] = vp[i];
#pragma unroll
                for (int kx = 0; kx < 3; kx++) {
                    const float4* wp = (const float4*)&sw[(ci * 9 + ky * 3 + kx) * 32 + kt * 8];
                    float4 w0 = wp[0], w1 = wp[1];
                    float wv[8] = {w0.x, w0.y, w0.z, w0.w, w1.x, w1.y, w1.z, w1.w};
#pragma unroll
                    for (int j = 0; j < 8; j++) {
                        float vv = v[kx + j];
#pragma unroll
                        for (int oo = 0; oo < 8; oo++)
                            acc[j * 8 + oo] = fmaf(vv, wv[oo], acc[j * 8 + oo]);
                    }
                }
            }
        }
    }
    int oy = 32 * ty + r, ox0 = 16 * tx + 8 * h;
#pragma unroll
    for (int oo = 0; oo < 8; oo++) {
        int o = kt * 8 + oo;
        float bb = b[o];
        float* op = g_d1 + ((n * 32 + o) * 64 + oy) * 64 + ox0;
#pragma unroll
        for (int j = 0; j < 8; j++)
            op[j] = fmaxf(acc[j * 8 + oo] + bb, 0.f);
    }
}

// d2: conv_t 32->64, k4 s2 p1. g_d1 -> g_d2(64,64,128,128).
// Parity-plane GEMM: block = one (y,x)-parity, 16x16 plane tile, 64 oc.
// 256 thr = 32 pos-groups(8) x 8 oc-groups(8). K = 32ci x 4 taps.
#define D2_IN_FL (32 * 17 * 18)   // 9792
#define D2_W_FL  (4 * 32 * 64)    // 8192
#define D2_SMEM_B ((D2_IN_FL + D2_W_FL) * 4)
__global__ __launch_bounds__(256, 2) void k_d2(const float* __restrict__ w,
                                               const float* __restrict__ b) {
    extern __shared__ float sm[];
    float* sIn = sm;             // [ci][17][18]
    float* sw  = sm + D2_IN_FL;  // [t4][ci][o64]
    int tid = threadIdx.x;
    int kt = tid & 7;            // oc group
    int pt = tid >> 3;           // 0..31
    int Yr = pt >> 1, h = pt & 1;
    int bx = blockIdx.x;
    int pe = bx >> 4;
    int e = pe >> 1, f = pe & 1;
    int tile = bx & 15;
    int tY = tile >> 2, tX = tile & 3;
    int n = blockIdx.y;
    int py = 1 - e, px = 1 - f;
    int iy0 = 16 * tY + e - 1, ix0 = 16 * tX + f - 1;
    for (int idx = tid; idx < 32 * 17 * 17; idx += 256) {
        int ci = idx / 289, rr = idx - ci * 289;
        int iy = rr / 17, ix = rr - iy * 17;
        int gy = iy0 + iy, gx = ix0 + ix;
        float v = 0.f;
        if (gy >= 0 && gy < 64 && gx >= 0 && gx < 64)
            v = g_d1[((n * 32 + ci) * 64 + gy) * 64 + gx];
        sIn[ci * 306 + iy * 18 + ix] = v;
    }
    for (int idx = tid; idx < D2_W_FL; idx += 256) {
        int t4 = idx >> 11, ci = (idx >> 6) & 31, o = idx & 63;
        int tky = t4 >> 1, tkx = t4 & 1;
        sw[idx] = w[(ci * 64 + o) * 16 + (py + 2 * tky) * 4 + (px + 2 * tkx)];
    }
    __syncthreads();
    float acc[64];
#pragma unroll
    for (int i = 0; i < 64; i++) acc[i] = 0.f;
#pragma unroll 4
    for (int ci = 0; ci < 32; ci++) {
        const float* pa = &sIn[ci * 306 + (Yr + 1) * 18 + 8 * h];
        const float* pb = pa - 18;
        float va[9], vb[9];
#pragma unroll
        for (int i = 0; i < 9; i++) { va[i] = pa[i]; vb[i] = pb[i]; }
#pragma unroll
        for (int tky = 0; tky < 2; tky++) {
#pragma unroll
            for (int tkx = 0; tkx < 2; tkx++) {
                int t4 = tky * 2 + tkx;
                const float4* wp = (const float4*)&sw[(t4 * 32 + ci) * 64 + kt * 8];
                float4 w0 = wp[0], w1 = wp[1];
                float wv[8] = {w0.x, w0.y, w0.z, w0.w, w1.x, w1.y, w1.z, w1.w};
#pragma unroll
                for (int j = 0; j < 8; j++) {
                    float v = tky ? vb[j + 1 - tkx] : va[j + 1 - tkx];
#pragma unroll
                    for (int oo = 0; oo < 8; oo++)
                        acc[j * 8 + oo] = fmaf(v, wv[oo], acc[j * 8 + oo]);
                }
            }
        }
    }
    int y = 32 * tY + 2 * Yr + e;
    int xbase = 32 * tX + 16 * h + f;
#pragma unroll
    for (int oo = 0; oo < 8; oo++) {
        int o = kt * 8 + oo;
        float bb = b[o];
        float* op = g_d2 + ((n * 64 + o) * 128 + y) * 128 + xbase;
#pragma unroll
        for (int j = 0; j < 8; j++)
            op[2 * j] = fmaxf(acc[j * 8 + oo] + bb, 0.f);
    }
}

// d3: conv_t 64->1, k4 s2 p1 -> x_hat
__global__ __launch_bounds__(256) void k_d3(const float* __restrict__ w,
                                            const float* __restrict__ b,
                                            float* __restrict__ xh) {
    __shared__ float sIn[6400];
    __shared__ float sw[1024];
    int tid = threadIdx.x;
    int sy = tid >> 4, sx = tid & 15;
    int tb = blockIdx.x;
    int tx = tb & 15, ty = tb >> 4;
    int n = blockIdx.y;
    int iy0 = 8 * ty - 1, ix0 = 8 * tx - 1;
    for (int e = tid; e < 6400; e += 256) {
        int ci = e / 100, r = e - ci * 100;
        int iy = r / 10, ix = r - iy * 10;
        int gy = iy0 + iy, gx = ix0 + ix;
        float v = 0.f;
        if (gy >= 0 && gy < 128 && gx >= 0 && gx < 128)
            v = g_d2[((n * 64 + ci) * 128 + gy) * 128 + gx];
        sIn[e] = v;
    }
    for (int e = tid; e < 1024; e += 256) sw[e] = w[e];
    __syncthreads();
    int y = 16 * ty + sy, x = 16 * tx + sx;
    int py = (y + 1) & 1, px = (x + 1) & 1;
    int iya = ((sy + 1 - py) >> 1) + 1, ixa = ((sx + 1 - px) >> 1) + 1;
    float acc = b[0];
#pragma unroll 8
    for (int ci = 0; ci < 64; ci++) {
#pragma unroll
        for (int t_y = 0; t_y < 2; t_y++) {
            int ky = py + 2 * t_y, iyl = iya - t_y;
#pragma unroll
            for (int t_x = 0; t_x < 2; t_x++) {
                int kx = px + 2 * t_x, ixl = ixa - t_x;
                acc = fmaf(sIn[ci * 100 + iyl * 10 + ixl], sw[ci * 16 + ky * 4 + kx], acc);
            }
        }
    }
    xh[n * 65536 + y * 256 + x] = acc;
}

// ---------------------------------------------------------------------------
extern "C" void kernel_launch(void* const* d_in, const int* in_sizes, int n_in,
                              void* d_out, int out_size) {
    const float* x   = (const float*)d_in[0];
    const float* e1w = (const float*)d_in[1];
    const float* e1b = (const float*)d_in[2];
    const float* e2w = (const float*)d_in[3];
    const float* e2b = (const float*)d_in[4];
    const float* e3w = (const float*)d_in[5];
    const float* e3b = (const float*)d_in[6];
    const float* emb = (const float*)d_in[7];
    const float* d1w = (const float*)d_in[8];
    const float* d1b = (const float*)d_in[9];
    const float* d2w = (const float*)d_in[10];
    const float* d2b = (const float*)d_in[11];
    const float* d3w = (const float*)d_in[12];
    const float* d3b = (const float*)d_in[13];
    float* out = (float*)d_out;
    float* ze = out + OFF_ZE;
    float* zq = out + OFF_ZQ;

    cudaFuncSetAttribute(k_e2, cudaFuncAttributeMaxDynamicSharedMemorySize, E2_SMEM_B);
    cudaFuncSetAttribute(k_e3, cudaFuncAttributeMaxDynamicSharedMemorySize, E3_SMEM_B);
    cudaFuncSetAttribute(k_vq, cudaFuncAttributeMaxDynamicSharedMemorySize, VQ_SMEM_B);
    cudaFuncSetAttribute(k_d1, cudaFuncAttributeMaxDynamicSharedMemorySize, D1_SMEM_B);
    cudaFuncSetAttribute(k_d2, cudaFuncAttributeMaxDynamicSharedMemorySize, D2_SMEM_B);

    k_e1<<<4096, 256>>>(x, e1w, e1b);
    k_e2<<<dim3(16, 64), 256, E2_SMEM_B>>>(e2w, e2b);
    k_e3<<<dim3(16, 64), 256, E3_SMEM_B>>>(e3w, e3b, ze);
    k_vq<<<2048, 256, VQ_SMEM_B>>>(ze, emb, zq);
    k_d1<<<dim3(8, 64), 256, D1_SMEM_B>>>(d1w, d1b);
    k_d2<<<dim3(64, 64), 256, D2_SMEM_B>>>(d2w, d2b);
    k_d3<<<dim3(256, 64), 256>>>(d3w, d3b, out);
}